// round 9
// baseline (speedup 1.0000x reference)
#include <cuda_runtime.h>

#define Bx 64
#define Pz 32
#define ATTR 7
#define Cc 224      // A*P*ATTR
#define Rr 4096
#define NLAB 32
#define GRID 512
#define TPB 256
#define ROW_BYTES 16384          // one conf row: 4096 f32
#define STAGES 4                 // rows per block

// accumulators: xy, wl, rot, obj, noobj (zero-init at load; reset by last block each call)
__device__ double g_acc[5];
__device__ unsigned int g_done;

__device__ __forceinline__ float softplus_fast(float x) {
    return fmaxf(x, 0.0f) + __logf(1.0f + __expf(-fabsf(x)));
}
__device__ __forceinline__ float tanh_approx(float x) {
    float y;
    asm("tanh.approx.f32 %0, %1;" : "=f"(y) : "f"(x));
    return y;
}
__device__ __forceinline__ float sigmoid_fast(float x) {
    return 1.0f / (1.0f + __expf(-x));
}
__device__ __forceinline__ unsigned smem_u32(const void* p) {
    return (unsigned)__cvta_generic_to_shared(p);
}

__global__ void __launch_bounds__(TPB) yolo_fused_kernel(
    const float* __restrict__ preds, const float* __restrict__ labels,
    float* __restrict__ out)
{
    __shared__ __align__(128) float4 buf[2][ROW_BYTES / 16];  // 2 x 16KB
    __shared__ __align__(8) unsigned long long mbar[2];
    __shared__ int s_key[32];
    __shared__ float red[TPB / 32];

    const int tid = threadIdx.x;

    // ---------- init mbarriers ----------
    if (tid == 0) {
        #pragma unroll
        for (int i = 0; i < 2; i++)
            asm volatile("mbarrier.init.shared.b64 [%0], 1;"
                         :: "r"(smem_u32(&mbar[i])) : "memory");
    }
    __syncthreads();

    // ---------- issue TMA bulk loads for stages 0 and 1 ----------
    // block owns conf rows [blockIdx.x*4, blockIdx.x*4+3]; row r -> image r>>5, ch r&31
    if (tid == 0) {
        #pragma unroll
        for (int s = 0; s < 2; s++) {
            int row = blockIdx.x * STAGES + s;
            const char* src = (const char*)preds
                + ((size_t)((row >> 5) * Cc + (row & 31) * ATTR + 6)) * ROW_BYTES;
            unsigned bar = smem_u32(&mbar[s]);
            asm volatile("mbarrier.arrive.expect_tx.shared.b64 _, [%0], %1;"
                         :: "r"(bar), "r"((unsigned)ROW_BYTES) : "memory");
            asm volatile(
                "cp.async.bulk.shared::cluster.global.mbarrier::complete_tx::bytes "
                "[%0], [%1], %2, [%3];"
                :: "r"(smem_u32(&buf[s][0])), "l"(src),
                   "r"((unsigned)ROW_BYTES), "r"(bar) : "memory");
        }
    }

    // ---------- Part 1: object-cell terms, overlapped with first TMA ----------
    if (blockIdx.x < Bx && tid < 32) {
        int bb = blockIdx.x, t = tid;
        const float* lab = labels + (bb * NLAB + t) * ATTR;
        float l0 = lab[0], l1 = lab[1], l2 = lab[2], l3 = lab[3],
              l4 = lab[4], l5 = lab[5];

        float ang = l0 + 204.8f;
        float q   = ang / 0.1f;
        int i = (int)floorf(q);
        i = min(max(i, 0), Rr - 1);
        float dq = l1;
        int j = (int)floorf(dq);
        j = min(max(j, 0), Pz - 1);

        int key = i * Pz + j;
        s_key[t] = key;
        __syncwarp();
        bool active = true;               // last-write-wins dedup
        for (int u = t + 1; u < 32; u++)
            if (s_key[u] == key) active = false;

        float sxy = 0.f, swl = 0.f, srot = 0.f, sobj = 0.f, scorr = 0.f;
        if (active) {
            const float* pp = preds + ((size_t)bb * Cc + (size_t)j * ATTR) * Rr + i;
            float x0 = pp[0 * Rr], x1 = pp[1 * Rr], x2 = pp[2 * Rr],
                  x3 = pp[3 * Rr], x4 = pp[4 * Rr], x5 = pp[5 * Rr],
                  x6 = pp[6 * Rr];

            float tx = q - (float)i;
            float ty = dq - (float)j;
            float sx = sigmoid_fast(x0);
            float sy = sigmoid_fast(x1);
            sxy = (sx - tx) * (sx - tx) + (sy - ty) * (sy - ty);

            float tw = __logf(l2 * 0.625f + 1e-16f);
            float tl = __logf(l3 * 0.2564102564f + 1e-16f);
            swl = (x2 - tw) * (x2 - tw) + (x3 - tl) * (x3 - tl);

            float r0 = tanh_approx(x4), r1 = tanh_approx(x5);
            srot = (r0 - l4) * (r0 - l4) + (r1 - l5) * (r1 - l5);

            sobj  = softplus_fast(-x6);
            scorr = -softplus_fast(x6);
        }
        #pragma unroll
        for (int off = 16; off; off >>= 1) {
            sxy   += __shfl_xor_sync(0xffffffffu, sxy,   off);
            swl   += __shfl_xor_sync(0xffffffffu, swl,   off);
            srot  += __shfl_xor_sync(0xffffffffu, srot,  off);
            sobj  += __shfl_xor_sync(0xffffffffu, sobj,  off);
            scorr += __shfl_xor_sync(0xffffffffu, scorr, off);
        }
        if (t == 0) {
            atomicAdd(&g_acc[0], (double)sxy);
            atomicAdd(&g_acc[1], (double)swl);
            atomicAdd(&g_acc[2], (double)srot);
            atomicAdd(&g_acc[3], (double)sobj);
            atomicAdd(&g_acc[4], (double)scorr);
        }
    }

    // ---------- Part 2: staged dense noobj BCE ----------
    float acc = 0.f;
    #pragma unroll
    for (int s = 0; s < STAGES; s++) {
        int bb = s & 1;
        unsigned bar = smem_u32(&mbar[bb]);
        unsigned phase = (s >> 1) & 1;
        // wait for stage s data
        {
            unsigned done;
            asm volatile(
                "{\n\t.reg .pred p;\n\t"
                "mbarrier.try_wait.parity.acquire.cta.shared::cta.b64 p, [%1], %2;\n\t"
                "selp.b32 %0, 1, 0, p;\n\t}"
                : "=r"(done) : "r"(bar), "r"(phase) : "memory");
            if (!done) {
                asm volatile(
                    "{\n\t.reg .pred P1;\n\t"
                    "WL_%=:\n\t"
                    "mbarrier.try_wait.parity.acquire.cta.shared::cta.b64 P1, [%0], %1, 0x989680;\n\t"
                    "@P1 bra.uni WD_%=;\n\t"
                    "bra.uni WL_%=;\n\t"
                    "WD_%=:\n\t}"
                    :: "r"(bar), "r"(phase) : "memory");
            }
        }
        // consume: 1024 float4, 256 threads x 4 (conflict-free LDS.128)
        float4 d0 = buf[bb][tid];
        float4 d1 = buf[bb][tid + 256];
        float4 d2 = buf[bb][tid + 512];
        float4 d3 = buf[bb][tid + 768];
        acc += softplus_fast(d0.x) + softplus_fast(d0.y)
             + softplus_fast(d0.z) + softplus_fast(d0.w);
        acc += softplus_fast(d1.x) + softplus_fast(d1.y)
             + softplus_fast(d1.z) + softplus_fast(d1.w);
        acc += softplus_fast(d2.x) + softplus_fast(d2.y)
             + softplus_fast(d2.z) + softplus_fast(d2.w);
        acc += softplus_fast(d3.x) + softplus_fast(d3.y)
             + softplus_fast(d3.z) + softplus_fast(d3.w);

        if (s + 2 < STAGES) {
            __syncthreads();              // all reads of buf[bb] done
            if (tid == 0) {
                asm volatile("fence.proxy.async.shared::cta;" ::: "memory");
                int row = blockIdx.x * STAGES + s + 2;
                const char* src = (const char*)preds
                    + ((size_t)((row >> 5) * Cc + (row & 31) * ATTR + 6)) * ROW_BYTES;
                asm volatile("mbarrier.arrive.expect_tx.shared.b64 _, [%0], %1;"
                             :: "r"(bar), "r"((unsigned)ROW_BYTES) : "memory");
                asm volatile(
                    "cp.async.bulk.shared::cluster.global.mbarrier::complete_tx::bytes "
                    "[%0], [%1], %2, [%3];"
                    :: "r"(smem_u32(&buf[bb][0])), "l"(src),
                       "r"((unsigned)ROW_BYTES), "r"(bar) : "memory");
            }
        }
    }

    // block reduction of dense sum
    #pragma unroll
    for (int off = 16; off; off >>= 1)
        acc += __shfl_xor_sync(0xffffffffu, acc, off);
    int wid = tid >> 5, lid = tid & 31;
    if (lid == 0) red[wid] = acc;
    __syncthreads();
    if (wid == 0) {
        acc = (lid < TPB / 32) ? red[lid] : 0.f;
        #pragma unroll
        for (int off = 4; off; off >>= 1)
            acc += __shfl_xor_sync(0xffffffffu, acc, off);
        if (lid == 0) atomicAdd(&g_acc[4], (double)acc);
    }

    // ---------- Part 3: last block finalizes + resets state ----------
    if (tid == 0) {
        __threadfence();
        unsigned prev = atomicAdd(&g_done, 1u);
        if (prev == GRID - 1) {
            __threadfence();
            double a0 = *((volatile double*)&g_acc[0]);
            double a1 = *((volatile double*)&g_acc[1]);
            double a2 = *((volatile double*)&g_acc[2]);
            double a3 = *((volatile double*)&g_acc[3]);
            double a4 = *((volatile double*)&g_acc[4]);
            float lxy = (float)a0, lwl = (float)a1, lrot = (float)a2,
                  lobj = (float)a3, lnoobj = (float)a4;
            out[0] = 10.0f * lxy + 10.0f * lwl + 20.0f * lrot +
                     20.0f * lobj + 1.0f * lnoobj;
            out[1] = lxy;
            out[2] = lwl;
            out[3] = lrot;
            out[4] = lobj;
            out[5] = lnoobj;
            g_acc[0] = 0.0; g_acc[1] = 0.0; g_acc[2] = 0.0;
            g_acc[3] = 0.0; g_acc[4] = 0.0;
            g_done = 0u;
            __threadfence();
        }
    }
}

extern "C" void kernel_launch(void* const* d_in, const int* in_sizes, int n_in,
                              void* d_out, int out_size) {
    const float* preds  = (const float*)d_in[0];
    const float* labels = (const float*)d_in[1];
    float* out = (float*)d_out;

    yolo_fused_kernel<<<GRID, TPB>>>(preds, labels, out);
}

// round 10
// speedup vs baseline: 1.1331x; 1.1331x over previous
#include <cuda_runtime.h>

#define Bx 64
#define Pz 32
#define ATTR 7
#define Cc 224      // A*P*ATTR
#define Rr 4096
#define NLAB 32
#define GRID 1024
#define TPB 256

// accumulators: xy, wl, rot, obj, noobj (zero-init at load; reset by last block each call)
__device__ double g_acc[5];
__device__ unsigned int g_done;

__device__ __forceinline__ float softplus_fast(float x) {
    return fmaxf(x, 0.0f) + __logf(1.0f + __expf(-fabsf(x)));
}
__device__ __forceinline__ float tanh_approx(float x) {
    float y;
    asm("tanh.approx.f32 %0, %1;" : "=f"(y) : "f"(x));
    return y;
}
__device__ __forceinline__ float sigmoid_fast(float x) {
    return 1.0f / (1.0f + __expf(-x));
}
// factor (1 + e^{-|x|}) = 1 + 2^{-|x|*log2(e)} : FMUL + MUFU.EX2 + FADD
__device__ __forceinline__ float sp_factor(float x) {
    return 1.0f + exp2f(-1.4426950408889634f * fabsf(x));
}

__global__ void __launch_bounds__(TPB) yolo_fused_kernel(
    const float* __restrict__ preds, const float* __restrict__ labels,
    float* __restrict__ out)
{
    __shared__ int s_key[32];
    __shared__ float red[TPB / 32];

    // ---------- Part 1: object-cell terms (blocks 0..63, warp 0) ----------
    if (blockIdx.x < Bx && threadIdx.x < 32) {
        int b = blockIdx.x, t = threadIdx.x;
        const float* lab = labels + (b * NLAB + t) * ATTR;
        float l0 = lab[0], l1 = lab[1], l2 = lab[2], l3 = lab[3],
              l4 = lab[4], l5 = lab[5];

        float ang = l0 + 204.8f;          // + R*CELL_ANGLE/2
        float q   = ang / 0.1f;           // / CELL_ANGLE
        int i = (int)floorf(q);
        i = min(max(i, 0), Rr - 1);
        float dq = l1;                    // / CELL_DEPTH (=1.0)
        int j = (int)floorf(dq);
        j = min(max(j, 0), Pz - 1);

        int key = i * Pz + j;
        s_key[t] = key;
        __syncwarp();
        bool active = true;               // last-write-wins dedup
        for (int u = t + 1; u < 32; u++)
            if (s_key[u] == key) active = false;

        float sxy = 0.f, swl = 0.f, srot = 0.f, sobj = 0.f, scorr = 0.f;
        if (active) {
            const float* pp = preds + ((size_t)b * Cc + (size_t)j * ATTR) * Rr + i;
            float x0 = pp[0 * Rr], x1 = pp[1 * Rr], x2 = pp[2 * Rr],
                  x3 = pp[3 * Rr], x4 = pp[4 * Rr], x5 = pp[5 * Rr],
                  x6 = pp[6 * Rr];

            float tx = q - (float)i;
            float ty = dq - (float)j;
            float sx = sigmoid_fast(x0);
            float sy = sigmoid_fast(x1);
            sxy = (sx - tx) * (sx - tx) + (sy - ty) * (sy - ty);

            float tw = __logf(l2 * 0.625f + 1e-16f);        // /1.6
            float tl = __logf(l3 * 0.2564102564f + 1e-16f); // /3.9
            swl = (x2 - tw) * (x2 - tw) + (x3 - tl) * (x3 - tl);

            float r0 = tanh_approx(x4), r1 = tanh_approx(x5);
            srot = (r0 - l4) * (r0 - l4) + (r1 - l5) * (r1 - l5);

            // -log(sigmoid(x)) = softplus(-x); log(1-sigmoid(x)) = -softplus(x)
            sobj  = softplus_fast(-x6);
            scorr = -softplus_fast(x6);   // remove this cell from dense noobj sum
        }
        #pragma unroll
        for (int off = 16; off; off >>= 1) {
            sxy   += __shfl_xor_sync(0xffffffffu, sxy,   off);
            swl   += __shfl_xor_sync(0xffffffffu, swl,   off);
            srot  += __shfl_xor_sync(0xffffffffu, srot,  off);
            sobj  += __shfl_xor_sync(0xffffffffu, sobj,  off);
            scorr += __shfl_xor_sync(0xffffffffu, scorr, off);
        }
        if (t == 0) {
            atomicAdd(&g_acc[0], (double)sxy);
            atomicAdd(&g_acc[1], (double)swl);
            atomicAdd(&g_acc[2], (double)srot);
            atomicAdd(&g_acc[3], (double)sobj);
            atomicAdd(&g_acc[4], (double)scorr);
        }
    }

    // ---------- Part 2: dense noobj BCE, row-local mapping (R4 structure) ----------
    // Sum softplus(x) = Sum max(x,0) + ln2 * Sum log2( prod_of_4 (1+e^{-|x|}) )
    // -> MUFU per element drops from 2.0 (EX2+LG2) to 1.25 (EX2 + LG2/4).
    // Products are depth-2 trees per float4; no long serial chains.
    {
        unsigned tid  = blockIdx.x * TPB + threadIdx.x;
        unsigned gw   = tid >> 5;            // global warp 0..8191
        unsigned lane = tid & 31;
        unsigned row  = gw >> 2;             // 0..2047  (= b*32 + ch)
        unsigned part = gw & 3;
        unsigned b    = row >> 5;
        unsigned ch   = row & 31;
        const float4* p4 = (const float4*)preds;
        const float4* bp = p4 + ((size_t)(b * Cc + ch * ATTR + 6)) * (Rr / 4)
                              + part * 256 + lane;

        float4 d0 = bp[0],   d1 = bp[32],  d2 = bp[64],  d3 = bp[96];
        float4 d4 = bp[128], d5 = bp[160], d6 = bp[192], d7 = bp[224];

        float m0 = 0.f, m1 = 0.f, m2 = 0.f, m3 = 0.f;   // sums of max(x,0)
        float gA = 0.f, gB = 0.f;                        // sums of log2(prod4)

        #define ACC4(d, m, g)                                                 \
        {                                                                     \
            m += (fmaxf((d).x, 0.f) + fmaxf((d).y, 0.f))                      \
               + (fmaxf((d).z, 0.f) + fmaxf((d).w, 0.f));                     \
            float fx = sp_factor((d).x), fy = sp_factor((d).y),               \
                  fz = sp_factor((d).z), fw = sp_factor((d).w);               \
            g += __log2f((fx * fy) * (fz * fw));                              \
        }

        ACC4(d0, m0, gA) ACC4(d1, m1, gB) ACC4(d2, m2, gA) ACC4(d3, m3, gB)
        ACC4(d4, m0, gA) ACC4(d5, m1, gB) ACC4(d6, m2, gA) ACC4(d7, m3, gB)
        #undef ACC4

        float s = ((m0 + m1) + (m2 + m3))
                + 0.6931471805599453f * (gA + gB);

        #pragma unroll
        for (int off = 16; off; off >>= 1)
            s += __shfl_xor_sync(0xffffffffu, s, off);
        int wid = threadIdx.x >> 5, lid = threadIdx.x & 31;
        if (lid == 0) red[wid] = s;
        __syncthreads();
        if (wid == 0) {
            s = (lid < TPB / 32) ? red[lid] : 0.f;
            #pragma unroll
            for (int off = 4; off; off >>= 1)
                s += __shfl_xor_sync(0xffffffffu, s, off);
            if (lid == 0) atomicAdd(&g_acc[4], (double)s);
        }
    }

    // ---------- Part 3: last block finalizes + resets state ----------
    if (threadIdx.x == 0) {
        __threadfence();
        unsigned prev = atomicAdd(&g_done, 1u);
        if (prev == GRID - 1) {
            __threadfence();
            double a0 = *((volatile double*)&g_acc[0]);
            double a1 = *((volatile double*)&g_acc[1]);
            double a2 = *((volatile double*)&g_acc[2]);
            double a3 = *((volatile double*)&g_acc[3]);
            double a4 = *((volatile double*)&g_acc[4]);
            float lxy = (float)a0, lwl = (float)a1, lrot = (float)a2,
                  lobj = (float)a3, lnoobj = (float)a4;
            out[0] = 10.0f * lxy + 10.0f * lwl + 20.0f * lrot +
                     20.0f * lobj + 1.0f * lnoobj;
            out[1] = lxy;
            out[2] = lwl;
            out[3] = lrot;
            out[4] = lobj;
            out[5] = lnoobj;
            g_acc[0] = 0.0; g_acc[1] = 0.0; g_acc[2] = 0.0;
            g_acc[3] = 0.0; g_acc[4] = 0.0;
            g_done = 0u;
            __threadfence();
        }
    }
}

extern "C" void kernel_launch(void* const* d_in, const int* in_sizes, int n_in,
                              void* d_out, int out_size) {
    const float* preds  = (const float*)d_in[0];
    const float* labels = (const float*)d_in[1];
    float* out = (float*)d_out;

    yolo_fused_kernel<<<GRID, TPB>>>(preds, labels, out);
}